// round 5
// baseline (speedup 1.0000x reference)
#include <cuda_runtime.h>
#include <cstdint>

// Problem constants (fixed by the dataset)
#define B_   4
#define NQ_  16384
#define C_   256
#define NH_  8
#define NP_  4
#define H_   128
#define W_   128
#define HD_  32
#define M_   (B_ * NQ_)      // 65536 rows
#define HW_  (H_ * W_)       // 16384

// Scratch (__device__ globals: allocation-free rule)
__device__ float g_qp     [(size_t)M_ * 128];       // [M, 64 off | 32 logits | 32 pad]
__device__ float g_vproj  [(size_t)B_ * HW_ * C_];  // [B, HW, C]
__device__ float g_sampled[(size_t)M_ * C_];        // [M, C]
__device__ float g_Wqpt   [128 * 256];              // [N=128 pad, K=256] tf32
__device__ float g_bqp    [128];
__device__ float g_Wvt    [256 * 256];              // W_v^T  [N,K] tf32
__device__ float g_Wot    [256 * 256];              // W_out^T [N,K] tf32

__device__ __forceinline__ uint32_t f2tf32(float x) {
    uint32_t r;
    asm("cvt.rna.tf32.f32 %0, %1;" : "=r"(r) : "f"(x));
    return r;
}

// m16n8k8 tf32 MMA (A row-major frag, B col-major frag), fp32 accumulate
__device__ __forceinline__ void mma_t(float* d, const uint32_t* a, const uint32_t* b) {
    asm volatile(
        "mma.sync.aligned.m16n8k8.row.col.f32.tf32.tf32.f32 "
        "{%0,%1,%2,%3}, {%4,%5,%6,%7}, {%8,%9}, {%0,%1,%2,%3};"
        : "+f"(d[0]), "+f"(d[1]), "+f"(d[2]), "+f"(d[3])
        : "r"(a[0]), "r"(a[1]), "r"(a[2]), "r"(a[3]), "r"(b[0]), "r"(b[1]));
}

// ---------------------------------------------------------------------------
// Pack kernels: transpose weights to [N,K] (K contiguous), round to tf32.
// ---------------------------------------------------------------------------
__global__ void pack_qp_t(const float* __restrict__ W_off, const float* __restrict__ b_off,
                          const float* __restrict__ W_attn, const float* __restrict__ b_attn)
{
    int idx = blockIdx.x * 256 + threadIdx.x;       // [0, 128*256)
    int n = idx >> 8, k = idx & 255;
    float v = 0.f;
    if (n < 64)       v = W_off[k * 64 + n];
    else if (n < 96)  v = W_attn[k * 32 + (n - 64)];
    g_Wqpt[idx] = __uint_as_float(f2tf32(v));
    if (idx < 128)
        g_bqp[idx] = (idx < 64) ? b_off[idx] : (idx < 96 ? b_attn[idx - 64] : 0.f);
}
__global__ void pack_t256(const float* __restrict__ W, float* __restrict__ dst)
{
    int idx = blockIdx.x * 256 + threadIdx.x;       // [0, 256*256)
    int n = idx >> 8, k = idx & 255;
    dst[idx] = __uint_as_float(f2tf32(W[k * 256 + n]));
}

// ---------------------------------------------------------------------------
// tf32 mma.sync GEMM: C[bm:bm+128, bn:bn+128] = A[M,256] @ Bt[N,256]^T + bias
// 256 threads = 8 warps (2 M x 4 N), warp tile 64x32, double-buffered K=32.
// Target 2 CTAs/SM (2 x 73.7KB smem, 2 x 32K regs).
// ---------------------------------------------------------------------------
#define PITCH 36   // floats; (4r+c)%32 distinct for r<8,c<8 -> conflict-free frags
static constexpr int GEMM_SMEM = 4 * 128 * PITCH * 4;   // 73728 B

__global__ __launch_bounds__(256, 2) void tf32_gemm(
    const float* __restrict__ A, const float* __restrict__ Bt,
    const float* __restrict__ bias, float* __restrict__ C, int Ncols)
{
    extern __shared__ float sm[];
    float* AsBase = sm;                          // [2][128][PITCH]
    float* BsBase = sm + 2 * 128 * PITCH;        // [2][128][PITCH]

    const int tid  = threadIdx.x;
    const int lane = tid & 31;
    const int wid  = tid >> 5;
    const int wm = (wid & 1) * 64;      // warp M offset within tile
    const int wn = (wid >> 1) * 32;     // warp N offset within tile
    const int bm = blockIdx.y * 128;
    const int bn = blockIdx.x * 128;

    const int qr = lane >> 2;           // 0..7
    const int qc = lane & 3;            // 0..3

    // global loaders: thread covers rows lr, lr+32, lr+64, lr+96 at col group lc
    const int lr = tid >> 3;            // 0..31
    const int lc = (tid & 7) * 4;       // 0..28

    const float* Ab = A  + (size_t)(bm + lr) * 256 + lc;
    const float* Bb = Bt + (size_t)(bn + lr) * 256 + lc;

    float acc[4][4][4];
    #pragma unroll
    for (int i = 0; i < 4; i++)
        #pragma unroll
        for (int j = 0; j < 4; j++)
            #pragma unroll
            for (int q = 0; q < 4; q++) acc[i][j][q] = 0.f;

    // chunk 0 -> buffer 0
    #pragma unroll
    for (int i = 0; i < 4; i++) {
        float4 va = *(const float4*)(Ab + (size_t)i * 32 * 256);
        float4 vb = *(const float4*)(Bb + (size_t)i * 32 * 256);
        float* ad = AsBase + (lr + i * 32) * PITCH + lc;
        float* bd = BsBase + (lr + i * 32) * PITCH + lc;
        ad[0] = __uint_as_float(f2tf32(va.x)); ad[1] = __uint_as_float(f2tf32(va.y));
        ad[2] = __uint_as_float(f2tf32(va.z)); ad[3] = __uint_as_float(f2tf32(va.w));
        *(float4*)bd = vb;
    }
    __syncthreads();

    float4 pa[4], pb[4];

    #pragma unroll 1
    for (int c = 0; c < 8; c++) {
        const float* Ac = AsBase + (c & 1) * 128 * PITCH;
        const float* Bc = BsBase + (c & 1) * 128 * PITCH;

        if (c < 7) {
            const int ko = (c + 1) * 32;
            #pragma unroll
            for (int i = 0; i < 4; i++) {
                pa[i] = *(const float4*)(Ab + (size_t)i * 32 * 256 + ko);
                pb[i] = *(const float4*)(Bb + (size_t)i * 32 * 256 + ko);
            }
        }

        #pragma unroll
        for (int ks = 0; ks < 4; ks++) {
            const int kc = ks * 8;
            uint32_t af[4][4], bf[4][2];
            #pragma unroll
            for (int i = 0; i < 4; i++) {
                const float* ap = Ac + (wm + i * 16 + qr) * PITCH + kc + qc;
                af[i][0] = __float_as_uint(ap[0]);
                af[i][1] = __float_as_uint(ap[8 * PITCH]);
                af[i][2] = __float_as_uint(ap[4]);
                af[i][3] = __float_as_uint(ap[8 * PITCH + 4]);
            }
            #pragma unroll
            for (int j = 0; j < 4; j++) {
                const float* bp = Bc + (wn + j * 8 + qr) * PITCH + kc + qc;
                bf[j][0] = __float_as_uint(bp[0]);
                bf[j][1] = __float_as_uint(bp[4]);
            }
            #pragma unroll
            for (int i = 0; i < 4; i++)
                #pragma unroll
                for (int j = 0; j < 4; j++)
                    mma_t(acc[i][j], af[i], bf[j]);
        }

        if (c < 7) {
            float* An = AsBase + ((c + 1) & 1) * 128 * PITCH;
            float* Bn = BsBase + ((c + 1) & 1) * 128 * PITCH;
            #pragma unroll
            for (int i = 0; i < 4; i++) {
                float* ad = An + (lr + i * 32) * PITCH + lc;
                float* bd = Bn + (lr + i * 32) * PITCH + lc;
                ad[0] = __uint_as_float(f2tf32(pa[i].x)); ad[1] = __uint_as_float(f2tf32(pa[i].y));
                ad[2] = __uint_as_float(f2tf32(pa[i].z)); ad[3] = __uint_as_float(f2tf32(pa[i].w));
                *(float4*)bd = pb[i];
            }
            __syncthreads();
        }
    }

    // Epilogue: c0/c1 at (row, col..col+1), c2/c3 at (row+8, col..col+1)
    #pragma unroll
    for (int i = 0; i < 4; i++) {
        const int r0 = bm + wm + i * 16 + qr;
        #pragma unroll
        for (int j = 0; j < 4; j++) {
            const int col = bn + wn + j * 8 + qc * 2;
            const float b0 = __ldg(&bias[col]), b1 = __ldg(&bias[col + 1]);
            float2 v0 = make_float2(acc[i][j][0] + b0, acc[i][j][1] + b1);
            float2 v1 = make_float2(acc[i][j][2] + b0, acc[i][j][3] + b1);
            *(float2*)(C + (size_t)r0 * Ncols + col) = v0;
            *(float2*)(C + (size_t)(r0 + 8) * Ncols + col) = v1;
        }
    }
}

// ---------------------------------------------------------------------------
// Sampler: warp covers 4 heads, float4 channels; branch-free clamped gathers
// so all 16 corner loads issue unconditionally (max MLP).
// ---------------------------------------------------------------------------
__global__ __launch_bounds__(256) void sample_kernel4(const float* __restrict__ ref)
{
    const int gw   = (blockIdx.x * 256 + threadIdx.x) >> 5;
    const int lane = threadIdx.x & 31;
    const int m     = gw >> 1;
    const int hbase = (gw & 1) << 2;
    const int g = lane >> 3;
    const int s = lane & 7;
    const int h = hbase + g;
    const int b = m >> 14;

    const float rx = __ldg(&ref[2 * m + 0]);
    const float ry = __ldg(&ref[2 * m + 1]);

    const float* qp = g_qp + (size_t)m * 128;

    const float4 lg = *(const float4*)(qp + 64 + h * 4);
    const float mx = fmaxf(fmaxf(lg.x, lg.y), fmaxf(lg.z, lg.w));
    const float e0 = __expf(lg.x - mx), e1 = __expf(lg.y - mx);
    const float e2 = __expf(lg.z - mx), e3 = __expf(lg.w - mx);
    const float inv = 1.f / (e0 + e1 + e2 + e3);
    const float w4[4] = {e0 * inv, e1 * inv, e2 * inv, e3 * inv};

    const float4 o01 = *(const float4*)(qp + h * 8);
    const float4 o23 = *(const float4*)(qp + h * 8 + 4);
    const float offx[4] = {o01.x, o01.z, o23.x, o23.z};
    const float offy[4] = {o01.y, o01.w, o23.y, o23.w};

    const float* vb = g_vproj + (size_t)b * HW_ * C_ + h * HD_ + s * 4;

    float ax = 0.f, ay = 0.f, az = 0.f, aw = 0.f;

    #pragma unroll
    for (int p = 0; p < 4; p++) {
        const float lx = fminf(fmaxf(rx + offx[p] * (0.1f / W_), 0.f), 1.f);
        const float ly = fminf(fmaxf(ry + offy[p] * (0.1f / H_), 0.f), 1.f);
        const float ixf = lx * (float)W_ - 0.5f;
        const float iyf = ly * (float)H_ - 0.5f;
        const float x0f = floorf(ixf), y0f = floorf(iyf);
        const float wx = ixf - x0f, wy = iyf - y0f;
        const int x0 = (int)x0f, y0 = (int)y0f;    // x0,y0 in [-1,127]

        // in-bounds masks as floats (x0<128, x1>=0, y0<128, y1>=0 always hold)
        const float mx0 = (x0 >= 0)      ? 1.f : 0.f;
        const float mx1 = (x0 + 1 < W_)  ? 1.f : 0.f;
        const float my0 = (y0 >= 0)      ? 1.f : 0.f;
        const float my1 = (y0 + 1 < H_)  ? 1.f : 0.f;

        // clamped coordinates (loads always valid)
        const int x0c = max(x0, 0),     x1c = min(x0 + 1, W_ - 1);
        const int y0c = max(y0, 0),     y1c = min(y0 + 1, H_ - 1);

        const float wp  = w4[p];
        const float c00 = wp * (1.f - wx) * (1.f - wy) * mx0 * my0;
        const float c10 = wp *        wx  * (1.f - wy) * mx1 * my0;
        const float c01 = wp * (1.f - wx) *        wy  * mx0 * my1;
        const float c11 = wp *        wx  *        wy  * mx1 * my1;

        const float* r0 = vb + (size_t)(y0c * W_) * C_;
        const float* r1 = vb + (size_t)(y1c * W_) * C_;
        const float4 v00 = *(const float4*)(r0 + (size_t)x0c * C_);
        const float4 v10 = *(const float4*)(r0 + (size_t)x1c * C_);
        const float4 v01 = *(const float4*)(r1 + (size_t)x0c * C_);
        const float4 v11 = *(const float4*)(r1 + (size_t)x1c * C_);

        ax = fmaf(c00, v00.x, fmaf(c10, v10.x, fmaf(c01, v01.x, fmaf(c11, v11.x, ax))));
        ay = fmaf(c00, v00.y, fmaf(c10, v10.y, fmaf(c01, v01.y, fmaf(c11, v11.y, ay))));
        az = fmaf(c00, v00.z, fmaf(c10, v10.z, fmaf(c01, v01.z, fmaf(c11, v11.z, az))));
        aw = fmaf(c00, v00.w, fmaf(c10, v10.w, fmaf(c01, v01.w, fmaf(c11, v11.w, aw))));
    }

    *(float4*)(g_sampled + (size_t)m * C_ + h * HD_ + s * 4) = make_float4(ax, ay, az, aw);
}

// ---------------------------------------------------------------------------
extern "C" void kernel_launch(void* const* d_in, const int* in_sizes, int n_in,
                              void* d_out, int out_size)
{
    const float* query  = (const float*)d_in[0];
    const float* refp   = (const float*)d_in[1];
    const float* value  = (const float*)d_in[2];
    const float* W_off  = (const float*)d_in[3];
    const float* b_off  = (const float*)d_in[4];
    const float* W_attn = (const float*)d_in[5];
    const float* b_attn = (const float*)d_in[6];
    const float* W_v    = (const float*)d_in[7];
    const float* b_v    = (const float*)d_in[8];
    const float* W_out  = (const float*)d_in[9];
    const float* b_out  = (const float*)d_in[10];
    float* out = (float*)d_out;

    float *p_qp, *p_vp, *p_s, *p_Wqpt, *p_bqp, *p_Wvt, *p_Wot;
    cudaGetSymbolAddress((void**)&p_qp,   g_qp);
    cudaGetSymbolAddress((void**)&p_vp,   g_vproj);
    cudaGetSymbolAddress((void**)&p_s,    g_sampled);
    cudaGetSymbolAddress((void**)&p_Wqpt, g_Wqpt);
    cudaGetSymbolAddress((void**)&p_bqp,  g_bqp);
    cudaGetSymbolAddress((void**)&p_Wvt,  g_Wvt);
    cudaGetSymbolAddress((void**)&p_Wot,  g_Wot);

    cudaFuncSetAttribute(tf32_gemm, cudaFuncAttributeMaxDynamicSharedMemorySize, GEMM_SMEM);

    // 0) pack/transpose/round weights
    pack_qp_t<<<128, 256>>>(W_off, b_off, W_attn, b_attn);
    pack_t256<<<256, 256>>>(W_v, p_Wvt);
    pack_t256<<<256, 256>>>(W_out, p_Wot);
    // 1) fused offset+logit projection: [M,256] x [256,128pad] -> g_qp (pitch 128)
    tf32_gemm<<<dim3(1, M_ / 128), 256, GEMM_SMEM>>>(query, p_Wqpt, p_bqp, p_qp, 128);
    // 2) value projection: [M,256] x [256,256]
    tf32_gemm<<<dim3(2, M_ / 128), 256, GEMM_SMEM>>>(value, p_Wvt, b_v, p_vp, 256);
    // 3) softmax + bilinear deformable sampling
    sample_kernel4<<<(M_ * 2 * 32) / 256, 256>>>(refp);
    // 4) output projection -> d_out
    tf32_gemm<<<dim3(2, M_ / 128), 256, GEMM_SMEM>>>(p_s, p_Wot, b_out, out, 256);
}

// round 6
// speedup vs baseline: 1.0163x; 1.0163x over previous
#include <cuda_runtime.h>
#include <cstdint>

// Problem constants (fixed by the dataset)
#define B_   4
#define NQ_  16384
#define C_   256
#define NH_  8
#define NP_  4
#define H_   128
#define W_   128
#define HD_  32
#define M_   (B_ * NQ_)      // 65536 rows
#define HW_  (H_ * W_)       // 16384

// Scratch (__device__ globals: allocation-free rule)
__device__ float g_qp     [(size_t)M_ * 128];       // [M, 64 off | 32 logits | 32 pad]
__device__ float g_vproj  [(size_t)B_ * HW_ * C_];  // [B, HW, C]
__device__ float g_sampled[(size_t)M_ * C_];        // [M, C]
__device__ float g_Wqpt   [128 * 256];              // [N=128 pad, K=256] tf32
__device__ float g_bqp    [128];
__device__ float g_Wvt    [256 * 256];              // W_v^T  [N,K] tf32
__device__ float g_Wot    [256 * 256];              // W_out^T [N,K] tf32

__device__ __forceinline__ uint32_t f2tf32(float x) {
    uint32_t r;
    asm("cvt.rna.tf32.f32 %0, %1;" : "=r"(r) : "f"(x));
    return r;
}
__device__ __forceinline__ uint32_t smem_u32(const void* p) {
    uint32_t a;
    asm("{ .reg .u64 t; cvta.to.shared.u64 t, %1; cvt.u32.u64 %0, t; }" : "=r"(a) : "l"(p));
    return a;
}
__device__ __forceinline__ void cp16(uint32_t dst, const void* src) {
    asm volatile("cp.async.cg.shared.global [%0], [%1], 16;" :: "r"(dst), "l"(src));
}

// m16n8k8 tf32 MMA (A row-major frag, B col-major frag), fp32 accumulate
__device__ __forceinline__ void mma_t(float* d, const uint32_t* a, const uint32_t* b) {
    asm volatile(
        "mma.sync.aligned.m16n8k8.row.col.f32.tf32.tf32.f32 "
        "{%0,%1,%2,%3}, {%4,%5,%6,%7}, {%8,%9}, {%0,%1,%2,%3};"
        : "+f"(d[0]), "+f"(d[1]), "+f"(d[2]), "+f"(d[3])
        : "r"(a[0]), "r"(a[1]), "r"(a[2]), "r"(a[3]), "r"(b[0]), "r"(b[1]));
}

// ---------------------------------------------------------------------------
// Pack kernels: transpose weights to [N,K] (K contiguous), round to tf32.
// ---------------------------------------------------------------------------
__global__ void pack_qp_t(const float* __restrict__ W_off, const float* __restrict__ b_off,
                          const float* __restrict__ W_attn, const float* __restrict__ b_attn)
{
    int idx = blockIdx.x * 256 + threadIdx.x;       // [0, 128*256)
    int n = idx >> 8, k = idx & 255;
    float v = 0.f;
    if (n < 64)       v = W_off[k * 64 + n];
    else if (n < 96)  v = W_attn[k * 32 + (n - 64)];
    g_Wqpt[idx] = __uint_as_float(f2tf32(v));
    if (idx < 128)
        g_bqp[idx] = (idx < 64) ? b_off[idx] : (idx < 96 ? b_attn[idx - 64] : 0.f);
}
__global__ void pack_t256(const float* __restrict__ W, float* __restrict__ dst)
{
    int idx = blockIdx.x * 256 + threadIdx.x;       // [0, 256*256)
    int n = idx >> 8, k = idx & 255;
    dst[idx] = __uint_as_float(f2tf32(W[k * 256 + n]));
}

// ---------------------------------------------------------------------------
// tf32 mma.sync GEMM: C[bm:bm+128, bn:bn+128] = A[M,256] @ Bt[N,256]^T + bias
// 128 threads = 4 warps (2 M x 2 N), warp tile 64x64 (i=4, j=8).
// cp.async double-buffered K chunks of 32. A raw fp32 in smem, cvt at frag load.
// ---------------------------------------------------------------------------
#define PITCH 36   // floats; (4r+c)%32 distinct for r<8,c<8 -> conflict-free frags
static constexpr int GEMM_SMEM = 4 * 128 * PITCH * 4;   // 73728 B

__global__ __launch_bounds__(128) void tf32_gemm(
    const float* __restrict__ A, const float* __restrict__ Bt,
    const float* __restrict__ bias, float* __restrict__ C, int Ncols)
{
    extern __shared__ float sm[];
    float* AsBase = sm;                          // [2][128][PITCH] raw fp32
    float* BsBase = sm + 2 * 128 * PITCH;        // [2][128][PITCH] tf32
    const uint32_t AsU = smem_u32(AsBase);
    const uint32_t BsU = smem_u32(BsBase);

    const int tid  = threadIdx.x;
    const int lane = tid & 31;
    const int wid  = tid >> 5;
    const int wm = (wid & 1) * 64;      // warp M offset within tile
    const int wn = (wid >> 1) * 64;     // warp N offset within tile
    const int bm = blockIdx.y * 128;
    const int bn = blockIdx.x * 128;

    const int qr = lane >> 2;           // 0..7
    const int qc = lane & 3;            // 0..3

    const float* Abase = A  + (size_t)bm * 256;
    const float* Bbase = Bt + (size_t)bn * 256;

    float acc[4][8][4];
    #pragma unroll
    for (int i = 0; i < 4; i++)
        #pragma unroll
        for (int j = 0; j < 8; j++)
            #pragma unroll
            for (int q = 0; q < 4; q++) acc[i][j][q] = 0.f;

    // async loader: 1024 16B units per matrix per chunk; 8 per thread each
    auto issue_chunk = [&](int c, int buf) {
        const uint32_t abuf = AsU + buf * 128 * PITCH * 4;
        const uint32_t bbuf = BsU + buf * 128 * PITCH * 4;
        #pragma unroll
        for (int o = 0; o < 8; o++) {
            const int u   = tid + o * 128;
            const int row = u >> 3, seg = u & 7;
            const uint32_t doff = (uint32_t)(row * PITCH + seg * 4) * 4;
            cp16(abuf + doff, Abase + (size_t)row * 256 + c * 32 + seg * 4);
            cp16(bbuf + doff, Bbase + (size_t)row * 256 + c * 32 + seg * 4);
        }
        asm volatile("cp.async.commit_group;");
    };

    issue_chunk(0, 0);

    #pragma unroll 1
    for (int c = 0; c < 8; c++) {
        if (c < 7) {
            issue_chunk(c + 1, (c + 1) & 1);
            asm volatile("cp.async.wait_group %0;" :: "n"(1));
        } else {
            asm volatile("cp.async.wait_group %0;" :: "n"(0));
        }
        __syncthreads();

        const float* Ac = AsBase + (c & 1) * 128 * PITCH;
        const float* Bc = BsBase + (c & 1) * 128 * PITCH;

        #pragma unroll
        for (int ks = 0; ks < 4; ks++) {
            const int kc = ks * 8;
            uint32_t af[4][4], bf[8][2];
            #pragma unroll
            for (int i = 0; i < 4; i++) {
                const float* ap = Ac + (wm + i * 16 + qr) * PITCH + kc + qc;
                af[i][0] = f2tf32(ap[0]);
                af[i][1] = f2tf32(ap[8 * PITCH]);
                af[i][2] = f2tf32(ap[4]);
                af[i][3] = f2tf32(ap[8 * PITCH + 4]);
            }
            #pragma unroll
            for (int j = 0; j < 8; j++) {
                const float* bp = Bc + (wn + j * 8 + qr) * PITCH + kc + qc;
                bf[j][0] = __float_as_uint(bp[0]);
                bf[j][1] = __float_as_uint(bp[4]);
            }
            #pragma unroll
            for (int i = 0; i < 4; i++)
                #pragma unroll
                for (int j = 0; j < 8; j++)
                    mma_t(acc[i][j], af[i], bf[j]);
        }
        __syncthreads();
    }

    // Epilogue: c0/c1 at (row, col..col+1), c2/c3 at (row+8, col..col+1)
    #pragma unroll
    for (int i = 0; i < 4; i++) {
        const int r0 = bm + wm + i * 16 + qr;
        #pragma unroll
        for (int j = 0; j < 8; j++) {
            const int col = bn + wn + j * 8 + qc * 2;
            const float b0 = __ldg(&bias[col]), b1 = __ldg(&bias[col + 1]);
            float2 v0 = make_float2(acc[i][j][0] + b0, acc[i][j][1] + b1);
            float2 v1 = make_float2(acc[i][j][2] + b0, acc[i][j][3] + b1);
            *(float2*)(C + (size_t)r0 * Ncols + col) = v0;
            *(float2*)(C + (size_t)(r0 + 8) * Ncols + col) = v1;
        }
    }
}

// ---------------------------------------------------------------------------
// Sampler: warp covers 4 heads, float4 channels; branch-free clamped gathers.
// ---------------------------------------------------------------------------
__global__ __launch_bounds__(256) void sample_kernel4(const float* __restrict__ ref)
{
    const int gw   = (blockIdx.x * 256 + threadIdx.x) >> 5;
    const int lane = threadIdx.x & 31;
    const int m     = gw >> 1;
    const int hbase = (gw & 1) << 2;
    const int g = lane >> 3;
    const int s = lane & 7;
    const int h = hbase + g;
    const int b = m >> 14;

    const float rx = __ldg(&ref[2 * m + 0]);
    const float ry = __ldg(&ref[2 * m + 1]);

    const float* qp = g_qp + (size_t)m * 128;

    const float4 lg = *(const float4*)(qp + 64 + h * 4);
    const float mx = fmaxf(fmaxf(lg.x, lg.y), fmaxf(lg.z, lg.w));
    const float e0 = __expf(lg.x - mx), e1 = __expf(lg.y - mx);
    const float e2 = __expf(lg.z - mx), e3 = __expf(lg.w - mx);
    const float inv = 1.f / (e0 + e1 + e2 + e3);
    const float w4[4] = {e0 * inv, e1 * inv, e2 * inv, e3 * inv};

    const float4 o01 = *(const float4*)(qp + h * 8);
    const float4 o23 = *(const float4*)(qp + h * 8 + 4);
    const float offx[4] = {o01.x, o01.z, o23.x, o23.z};
    const float offy[4] = {o01.y, o01.w, o23.y, o23.w};

    const float* vb = g_vproj + (size_t)b * HW_ * C_ + h * HD_ + s * 4;

    float ax = 0.f, ay = 0.f, az = 0.f, aw = 0.f;

    #pragma unroll
    for (int p = 0; p < 4; p++) {
        const float lx = fminf(fmaxf(rx + offx[p] * (0.1f / W_), 0.f), 1.f);
        const float ly = fminf(fmaxf(ry + offy[p] * (0.1f / H_), 0.f), 1.f);
        const float ixf = lx * (float)W_ - 0.5f;
        const float iyf = ly * (float)H_ - 0.5f;
        const float x0f = floorf(ixf), y0f = floorf(iyf);
        const float wx = ixf - x0f, wy = iyf - y0f;
        const int x0 = (int)x0f, y0 = (int)y0f;    // in [-1,127]

        const float mx0 = (x0 >= 0)      ? 1.f : 0.f;
        const float mx1 = (x0 + 1 < W_)  ? 1.f : 0.f;
        const float my0 = (y0 >= 0)      ? 1.f : 0.f;
        const float my1 = (y0 + 1 < H_)  ? 1.f : 0.f;

        const int x0c = max(x0, 0),     x1c = min(x0 + 1, W_ - 1);
        const int y0c = max(y0, 0),     y1c = min(y0 + 1, H_ - 1);

        const float wp  = w4[p];
        const float c00 = wp * (1.f - wx) * (1.f - wy) * mx0 * my0;
        const float c10 = wp *        wx  * (1.f - wy) * mx1 * my0;
        const float c01 = wp * (1.f - wx) *        wy  * mx0 * my1;
        const float c11 = wp *        wx  *        wy  * mx1 * my1;

        const float* r0 = vb + (size_t)(y0c * W_) * C_;
        const float* r1 = vb + (size_t)(y1c * W_) * C_;
        const float4 v00 = *(const float4*)(r0 + (size_t)x0c * C_);
        const float4 v10 = *(const float4*)(r0 + (size_t)x1c * C_);
        const float4 v01 = *(const float4*)(r1 + (size_t)x0c * C_);
        const float4 v11 = *(const float4*)(r1 + (size_t)x1c * C_);

        ax = fmaf(c00, v00.x, fmaf(c10, v10.x, fmaf(c01, v01.x, fmaf(c11, v11.x, ax))));
        ay = fmaf(c00, v00.y, fmaf(c10, v10.y, fmaf(c01, v01.y, fmaf(c11, v11.y, ay))));
        az = fmaf(c00, v00.z, fmaf(c10, v10.z, fmaf(c01, v01.z, fmaf(c11, v11.z, az))));
        aw = fmaf(c00, v00.w, fmaf(c10, v10.w, fmaf(c01, v01.w, fmaf(c11, v11.w, aw))));
    }

    *(float4*)(g_sampled + (size_t)m * C_ + h * HD_ + s * 4) = make_float4(ax, ay, az, aw);
}

// ---------------------------------------------------------------------------
extern "C" void kernel_launch(void* const* d_in, const int* in_sizes, int n_in,
                              void* d_out, int out_size)
{
    const float* query  = (const float*)d_in[0];
    const float* refp   = (const float*)d_in[1];
    const float* value  = (const float*)d_in[2];
    const float* W_off  = (const float*)d_in[3];
    const float* b_off  = (const float*)d_in[4];
    const float* W_attn = (const float*)d_in[5];
    const float* b_attn = (const float*)d_in[6];
    const float* W_v    = (const float*)d_in[7];
    const float* b_v    = (const float*)d_in[8];
    const float* W_out  = (const float*)d_in[9];
    const float* b_out  = (const float*)d_in[10];
    float* out = (float*)d_out;

    float *p_qp, *p_vp, *p_s, *p_Wqpt, *p_bqp, *p_Wvt, *p_Wot;
    cudaGetSymbolAddress((void**)&p_qp,   g_qp);
    cudaGetSymbolAddress((void**)&p_vp,   g_vproj);
    cudaGetSymbolAddress((void**)&p_s,    g_sampled);
    cudaGetSymbolAddress((void**)&p_Wqpt, g_Wqpt);
    cudaGetSymbolAddress((void**)&p_bqp,  g_bqp);
    cudaGetSymbolAddress((void**)&p_Wvt,  g_Wvt);
    cudaGetSymbolAddress((void**)&p_Wot,  g_Wot);

    cudaFuncSetAttribute(tf32_gemm, cudaFuncAttributeMaxDynamicSharedMemorySize, GEMM_SMEM);

    // 0) pack/transpose/round weights
    pack_qp_t<<<128, 256>>>(W_off, b_off, W_attn, b_attn);
    pack_t256<<<256, 256>>>(W_v, p_Wvt);
    pack_t256<<<256, 256>>>(W_out, p_Wot);
    // 1) fused offset+logit projection: [M,256] x [256,128pad] -> g_qp (pitch 128)
    tf32_gemm<<<dim3(1, M_ / 128), 128, GEMM_SMEM>>>(query, p_Wqpt, p_bqp, p_qp, 128);
    // 2) value projection: [M,256] x [256,256]
    tf32_gemm<<<dim3(2, M_ / 128), 128, GEMM_SMEM>>>(value, p_Wvt, b_v, p_vp, 256);
    // 3) softmax + bilinear deformable sampling
    sample_kernel4<<<(M_ * 2 * 32) / 256, 256>>>(refp);
    // 4) output projection -> d_out
    tf32_gemm<<<dim3(2, M_ / 128), 128, GEMM_SMEM>>>(p_s, p_Wot, b_out, out, 256);
}

// round 7
// speedup vs baseline: 1.2136x; 1.1942x over previous
#include <cuda_runtime.h>
#include <cuda_fp16.h>
#include <cstdint>

// Problem constants (fixed by the dataset)
#define B_   4
#define NQ_  16384
#define C_   256
#define NH_  8
#define NP_  4
#define H_   128
#define W_   128
#define HD_  32
#define M_   (B_ * NQ_)      // 65536 rows
#define HW_  (H_ * W_)       // 16384

// Scratch (__device__ globals: allocation-free rule)
__device__ float  g_qp     [(size_t)M_ * 128];       // [M, 64 off | 32 logits | pad]
__device__ float  g_vproj  [(size_t)B_ * HW_ * C_];  // [B, HW, C]
__device__ float  g_sampled[(size_t)M_ * C_];        // [M, C]
__device__ __half g_Wqpt_h [96 * 256];               // packed W_off|W_attn, [N,K] fp16
__device__ float  g_bqp    [96];
__device__ __half g_Wvt_h  [256 * 256];              // W_v^T  [N,K] fp16
__device__ __half g_Wot_h  [256 * 256];              // W_out^T [N,K] fp16

__device__ __forceinline__ uint32_t smem_u32(const void* p) {
    uint32_t a;
    asm("{ .reg .u64 t; cvta.to.shared.u64 t, %1; cvt.u32.u64 %0, t; }" : "=r"(a) : "l"(p));
    return a;
}
__device__ __forceinline__ void cp16(uint32_t dst, const void* src) {
    asm volatile("cp.async.cg.shared.global [%0], [%1], 16;" :: "r"(dst), "l"(src));
}
// pack two fp32 -> f16x2 (lo = first k, hi = second k)
__device__ __forceinline__ uint32_t pack_h2(float lo, float hi) {
    uint32_t r;
    asm("cvt.rn.f16x2.f32 %0, %1, %2;" : "=r"(r) : "f"(hi), "f"(lo));
    return r;
}

// m16n8k16 fp16 MMA, fp32 accumulate
__device__ __forceinline__ void mma_h(float* d, const uint32_t* a, const uint32_t* b) {
    asm volatile(
        "mma.sync.aligned.m16n8k16.row.col.f32.f16.f16.f32 "
        "{%0,%1,%2,%3}, {%4,%5,%6,%7}, {%8,%9}, {%0,%1,%2,%3};"
        : "+f"(d[0]), "+f"(d[1]), "+f"(d[2]), "+f"(d[3])
        : "r"(a[0]), "r"(a[1]), "r"(a[2]), "r"(a[3]), "r"(b[0]), "r"(b[1]));
}

// ---------------------------------------------------------------------------
// Pack kernels: transpose weights to [N,K] (K contiguous), convert to fp16.
// ---------------------------------------------------------------------------
__global__ void pack_qp_t(const float* __restrict__ W_off, const float* __restrict__ b_off,
                          const float* __restrict__ W_attn, const float* __restrict__ b_attn)
{
    int idx = blockIdx.x * 256 + threadIdx.x;       // [0, 96*256)
    int n = idx >> 8, k = idx & 255;
    float v = (n < 64) ? W_off[k * 64 + n] : W_attn[k * 32 + (n - 64)];
    g_Wqpt_h[idx] = __float2half_rn(v);
    if (idx < 96)
        g_bqp[idx] = (idx < 64) ? b_off[idx] : b_attn[idx - 64];
}
__global__ void pack_t256(const float* __restrict__ W, __half* __restrict__ dst)
{
    int idx = blockIdx.x * 256 + threadIdx.x;       // [0, 256*256)
    int n = idx >> 8, k = idx & 255;
    dst[idx] = __float2half_rn(W[k * 256 + n]);
}

// ---------------------------------------------------------------------------
// fp16 mma.sync GEMM: block tile 128 x (16*JT), 128 threads = 4 warps
// (2M x 2N), warp tile 64 x (8*JT). A fp32 in smem (cvt at frag load),
// B fp16 in smem. cp.async double-buffered K chunks of 32.
// ---------------------------------------------------------------------------
#define PITCHA 40   // floats per A row  (160B) -> conflict-free LDS.64 frags
#define PITCHB 40   // halves per B row  (80B)  -> conflict-free LDS.32 frags

template<int JT>    // j-tiles per N-warp; BN = 16*JT (128 or 96)
__global__ __launch_bounds__(128, 3) void h16_gemm(
    const float* __restrict__ A, const __half* __restrict__ Bt,
    const float* __restrict__ bias, float* __restrict__ C, int Ncols)
{
    constexpr int BN = 16 * JT;
    constexpr int ABUF = 128 * PITCHA;       // floats per A buffer
    constexpr int BBUF = BN * PITCHB;        // halves per B buffer

    extern __shared__ char smraw[];
    float*  As = (float*)smraw;                        // [2][128][PITCHA]
    __half* Bs = (__half*)(smraw + 2 * ABUF * 4);      // [2][BN][PITCHB]
    const uint32_t AsU = smem_u32(As);
    const uint32_t BsU = smem_u32(Bs);

    const int tid  = threadIdx.x;
    const int lane = tid & 31;
    const int wid  = tid >> 5;
    const int wm = (wid & 1) * 64;
    const int wn = (wid >> 1) * (8 * JT);
    const int bm = blockIdx.y * 128;
    const int bn = blockIdx.x * BN;

    const int qr = lane >> 2;           // 0..7
    const int qc = lane & 3;            // 0..3

    const float*  Abase = A  + (size_t)bm * 256;
    const __half* Bbase = Bt + (size_t)bn * 256;

    float acc[4][JT][4];
    #pragma unroll
    for (int i = 0; i < 4; i++)
        #pragma unroll
        for (int j = 0; j < JT; j++)
            #pragma unroll
            for (int q = 0; q < 4; q++) acc[i][j][q] = 0.f;

    auto issue_chunk = [&](int c, int buf) {
        const uint32_t abuf = AsU + buf * ABUF * 4;
        const uint32_t bbuf = BsU + buf * BBUF * 2;
        #pragma unroll
        for (int o = 0; o < 8; o++) {                 // A: 1024 x 16B units
            const int u = tid + o * 128;
            const int row = u >> 3, seg = u & 7;
            cp16(abuf + row * (PITCHA * 4) + seg * 16,
                 Abase + (size_t)row * 256 + c * 32 + seg * 4);
        }
        #pragma unroll
        for (int o = 0; o < BN / 32; o++) {           // B: BN*4 x 16B units
            const int u = tid + o * 128;
            const int row = u >> 2, seg = u & 3;
            cp16(bbuf + row * (PITCHB * 2) + seg * 16,
                 Bbase + (size_t)row * 256 + c * 32 + seg * 8);
        }
        asm volatile("cp.async.commit_group;");
    };

    issue_chunk(0, 0);

    #pragma unroll 1
    for (int c = 0; c < 8; c++) {
        if (c < 7) {
            issue_chunk(c + 1, (c + 1) & 1);
            asm volatile("cp.async.wait_group %0;" :: "n"(1));
        } else {
            asm volatile("cp.async.wait_group %0;" :: "n"(0));
        }
        __syncthreads();

        const float*  Ac = As + (c & 1) * ABUF;
        const __half* Bc = Bs + (c & 1) * BBUF;

        #pragma unroll
        for (int ks = 0; ks < 2; ks++) {              // K=16 per mma
            const int kc = ks * 16;
            uint32_t af[4][4], bf[JT][2];
            #pragma unroll
            for (int i = 0; i < 4; i++) {
                const float* ap = Ac + (wm + i * 16 + qr) * PITCHA + kc + 2 * qc;
                float2 p0 = *(const float2*)(ap);
                float2 p1 = *(const float2*)(ap + 8 * PITCHA);
                float2 p2 = *(const float2*)(ap + 8);
                float2 p3 = *(const float2*)(ap + 8 * PITCHA + 8);
                af[i][0] = pack_h2(p0.x, p0.y);
                af[i][1] = pack_h2(p1.x, p1.y);
                af[i][2] = pack_h2(p2.x, p2.y);
                af[i][3] = pack_h2(p3.x, p3.y);
            }
            #pragma unroll
            for (int j = 0; j < JT; j++) {
                const __half* bp = Bc + (wn + j * 8 + qr) * PITCHB + kc + 2 * qc;
                bf[j][0] = *(const uint32_t*)(bp);
                bf[j][1] = *(const uint32_t*)(bp + 8);
            }
            #pragma unroll
            for (int i = 0; i < 4; i++)
                #pragma unroll
                for (int j = 0; j < JT; j++)
                    mma_h(acc[i][j], af[i], bf[j]);
        }
        __syncthreads();
    }

    // Epilogue: c0/c1 at (row, col..col+1), c2/c3 at (row+8, col..col+1)
    #pragma unroll
    for (int i = 0; i < 4; i++) {
        const int r0 = bm + wm + i * 16 + qr;
        #pragma unroll
        for (int j = 0; j < JT; j++) {
            const int col = bn + wn + j * 8 + qc * 2;
            const float b0 = __ldg(&bias[col]), b1 = __ldg(&bias[col + 1]);
            float2 v0 = make_float2(acc[i][j][0] + b0, acc[i][j][1] + b1);
            float2 v1 = make_float2(acc[i][j][2] + b0, acc[i][j][3] + b1);
            *(float2*)(C + (size_t)r0 * Ncols + col) = v0;
            *(float2*)(C + (size_t)(r0 + 8) * Ncols + col) = v1;
        }
    }
}

static constexpr int SMEM_J8 = 2 * 128 * PITCHA * 4 + 2 * 128 * PITCHB * 2;  // 61440
static constexpr int SMEM_J6 = 2 * 128 * PITCHA * 4 + 2 * 96  * PITCHB * 2;  // 56320

// ---------------------------------------------------------------------------
// Sampler: warp covers 4 heads, float4 channels; branch-free clamped gathers.
// ---------------------------------------------------------------------------
__global__ __launch_bounds__(256) void sample_kernel4(const float* __restrict__ ref)
{
    const int gw   = (blockIdx.x * 256 + threadIdx.x) >> 5;
    const int lane = threadIdx.x & 31;
    const int m     = gw >> 1;
    const int hbase = (gw & 1) << 2;
    const int g = lane >> 3;
    const int s = lane & 7;
    const int h = hbase + g;
    const int b = m >> 14;

    const float rx = __ldg(&ref[2 * m + 0]);
    const float ry = __ldg(&ref[2 * m + 1]);

    const float* qp = g_qp + (size_t)m * 128;

    const float4 lg = *(const float4*)(qp + 64 + h * 4);
    const float mx = fmaxf(fmaxf(lg.x, lg.y), fmaxf(lg.z, lg.w));
    const float e0 = __expf(lg.x - mx), e1 = __expf(lg.y - mx);
    const float e2 = __expf(lg.z - mx), e3 = __expf(lg.w - mx);
    const float inv = 1.f / (e0 + e1 + e2 + e3);
    const float w4[4] = {e0 * inv, e1 * inv, e2 * inv, e3 * inv};

    const float4 o01 = *(const float4*)(qp + h * 8);
    const float4 o23 = *(const float4*)(qp + h * 8 + 4);
    const float offx[4] = {o01.x, o01.z, o23.x, o23.z};
    const float offy[4] = {o01.y, o01.w, o23.y, o23.w};

    const float* vb = g_vproj + (size_t)b * HW_ * C_ + h * HD_ + s * 4;

    float ax = 0.f, ay = 0.f, az = 0.f, aw = 0.f;

    #pragma unroll
    for (int p = 0; p < 4; p++) {
        const float lx = fminf(fmaxf(rx + offx[p] * (0.1f / W_), 0.f), 1.f);
        const float ly = fminf(fmaxf(ry + offy[p] * (0.1f / H_), 0.f), 1.f);
        const float ixf = lx * (float)W_ - 0.5f;
        const float iyf = ly * (float)H_ - 0.5f;
        const float x0f = floorf(ixf), y0f = floorf(iyf);
        const float wx = ixf - x0f, wy = iyf - y0f;
        const int x0 = (int)x0f, y0 = (int)y0f;    // in [-1,127]

        const float mx0 = (x0 >= 0)      ? 1.f : 0.f;
        const float mx1 = (x0 + 1 < W_)  ? 1.f : 0.f;
        const float my0 = (y0 >= 0)      ? 1.f : 0.f;
        const float my1 = (y0 + 1 < H_)  ? 1.f : 0.f;

        const int x0c = max(x0, 0),     x1c = min(x0 + 1, W_ - 1);
        const int y0c = max(y0, 0),     y1c = min(y0 + 1, H_ - 1);

        const float wp  = w4[p];
        const float c00 = wp * (1.f - wx) * (1.f - wy) * mx0 * my0;
        const float c10 = wp *        wx  * (1.f - wy) * mx1 * my0;
        const float c01 = wp * (1.f - wx) *        wy  * mx0 * my1;
        const float c11 = wp *        wx  *        wy  * mx1 * my1;

        const float* r0 = vb + (size_t)(y0c * W_) * C_;
        const float* r1 = vb + (size_t)(y1c * W_) * C_;
        const float4 v00 = *(const float4*)(r0 + (size_t)x0c * C_);
        const float4 v10 = *(const float4*)(r0 + (size_t)x1c * C_);
        const float4 v01 = *(const float4*)(r1 + (size_t)x0c * C_);
        const float4 v11 = *(const float4*)(r1 + (size_t)x1c * C_);

        ax = fmaf(c00, v00.x, fmaf(c10, v10.x, fmaf(c01, v01.x, fmaf(c11, v11.x, ax))));
        ay = fmaf(c00, v00.y, fmaf(c10, v10.y, fmaf(c01, v01.y, fmaf(c11, v11.y, ay))));
        az = fmaf(c00, v00.z, fmaf(c10, v10.z, fmaf(c01, v01.z, fmaf(c11, v11.z, az))));
        aw = fmaf(c00, v00.w, fmaf(c10, v10.w, fmaf(c01, v01.w, fmaf(c11, v11.w, aw))));
    }

    *(float4*)(g_sampled + (size_t)m * C_ + h * HD_ + s * 4) = make_float4(ax, ay, az, aw);
}

// ---------------------------------------------------------------------------
extern "C" void kernel_launch(void* const* d_in, const int* in_sizes, int n_in,
                              void* d_out, int out_size)
{
    const float* query  = (const float*)d_in[0];
    const float* refp   = (const float*)d_in[1];
    const float* value  = (const float*)d_in[2];
    const float* W_off  = (const float*)d_in[3];
    const float* b_off  = (const float*)d_in[4];
    const float* W_attn = (const float*)d_in[5];
    const float* b_attn = (const float*)d_in[6];
    const float* W_v    = (const float*)d_in[7];
    const float* b_v    = (const float*)d_in[8];
    const float* W_out  = (const float*)d_in[9];
    const float* b_out  = (const float*)d_in[10];
    float* out = (float*)d_out;

    float *p_qp, *p_vp, *p_s, *p_bqp;
    __half *p_Wqpt, *p_Wvt, *p_Wot;
    cudaGetSymbolAddress((void**)&p_qp,   g_qp);
    cudaGetSymbolAddress((void**)&p_vp,   g_vproj);
    cudaGetSymbolAddress((void**)&p_s,    g_sampled);
    cudaGetSymbolAddress((void**)&p_Wqpt, g_Wqpt_h);
    cudaGetSymbolAddress((void**)&p_bqp,  g_bqp);
    cudaGetSymbolAddress((void**)&p_Wvt,  g_Wvt_h);
    cudaGetSymbolAddress((void**)&p_Wot,  g_Wot_h);

    cudaFuncSetAttribute(h16_gemm<8>, cudaFuncAttributeMaxDynamicSharedMemorySize, SMEM_J8);
    cudaFuncSetAttribute(h16_gemm<6>, cudaFuncAttributeMaxDynamicSharedMemorySize, SMEM_J6);

    // 0) pack/transpose/convert weights
    pack_qp_t<<<96, 256>>>(W_off, b_off, W_attn, b_attn);
    pack_t256<<<256, 256>>>(W_v, p_Wvt);
    pack_t256<<<256, 256>>>(W_out, p_Wot);
    // 1) fused offset+logit projection: [M,256] x [256,96] -> g_qp (pitch 128)
    h16_gemm<6><<<dim3(1, M_ / 128), 128, SMEM_J6>>>(query, p_Wqpt, p_bqp, p_qp, 128);
    // 2) value projection: [M,256] x [256,256]
    h16_gemm<8><<<dim3(2, M_ / 128), 128, SMEM_J8>>>(value, p_Wvt, b_v, p_vp, 256);
    // 3) softmax + bilinear deformable sampling
    sample_kernel4<<<(M_ * 2 * 32) / 256, 256>>>(refp);
    // 4) output projection -> d_out
    h16_gemm<8><<<dim3(2, M_ / 128), 128, SMEM_J8>>>(p_s, p_Wot, b_out, out, 256);
}

// round 8
// speedup vs baseline: 1.2930x; 1.0655x over previous
#include <cuda_runtime.h>
#include <cuda_fp16.h>
#include <cstdint>

// Problem constants (fixed by the dataset)
#define B_   4
#define NQ_  16384
#define C_   256
#define NH_  8
#define NP_  4
#define H_   128
#define W_   128
#define HD_  32
#define M_   (B_ * NQ_)      // 65536 rows
#define HW_  (H_ * W_)       // 16384

// Scratch (__device__ globals: allocation-free rule)
__device__ float  g_qp       [(size_t)M_ * 128];       // [M, 64 off | 32 logits | pad]
__device__ float  g_vproj    [(size_t)B_ * HW_ * C_];  // [B, HW, C]
__device__ __half g_sampled_h[(size_t)M_ * C_];        // [M, C] fp16
__device__ __half g_Wqpt_h   [96 * 256];               // packed W_off|W_attn, [N,K] fp16
__device__ float  g_bqp      [96];
__device__ __half g_Wvt_h    [256 * 256];              // W_v^T  [N,K] fp16
__device__ __half g_Wot_h    [256 * 256];              // W_out^T [N,K] fp16

__device__ __forceinline__ uint32_t smem_u32(const void* p) {
    uint32_t a;
    asm("{ .reg .u64 t; cvta.to.shared.u64 t, %1; cvt.u32.u64 %0, t; }" : "=r"(a) : "l"(p));
    return a;
}
__device__ __forceinline__ void cp16(uint32_t dst, const void* src) {
    asm volatile("cp.async.cg.shared.global [%0], [%1], 16;" :: "r"(dst), "l"(src));
}
// pack two fp32 -> f16x2 (lo = first elem, hi = second)
__device__ __forceinline__ uint32_t pack_h2(float lo, float hi) {
    uint32_t r;
    asm("cvt.rn.f16x2.f32 %0, %1, %2;" : "=r"(r) : "f"(hi), "f"(lo));
    return r;
}

// m16n8k16 fp16 MMA, fp32 accumulate
__device__ __forceinline__ void mma_h(float* d, const uint32_t* a, const uint32_t* b) {
    asm volatile(
        "mma.sync.aligned.m16n8k16.row.col.f32.f16.f16.f32 "
        "{%0,%1,%2,%3}, {%4,%5,%6,%7}, {%8,%9}, {%0,%1,%2,%3};"
        : "+f"(d[0]), "+f"(d[1]), "+f"(d[2]), "+f"(d[3])
        : "r"(a[0]), "r"(a[1]), "r"(a[2]), "r"(a[3]), "r"(b[0]), "r"(b[1]));
}

// ---------------------------------------------------------------------------
// Pack kernels: transpose weights to [N,K] (K contiguous), convert to fp16.
// ---------------------------------------------------------------------------
__global__ void pack_qp_t(const float* __restrict__ W_off, const float* __restrict__ b_off,
                          const float* __restrict__ W_attn, const float* __restrict__ b_attn)
{
    int idx = blockIdx.x * 256 + threadIdx.x;       // [0, 96*256)
    int n = idx >> 8, k = idx & 255;
    float v = (n < 64) ? W_off[k * 64 + n] : W_attn[k * 32 + (n - 64)];
    g_Wqpt_h[idx] = __float2half_rn(v);
    if (idx < 96)
        g_bqp[idx] = (idx < 64) ? b_off[idx] : b_attn[idx - 64];
}
__global__ void pack_t256(const float* __restrict__ W, __half* __restrict__ dst)
{
    int idx = blockIdx.x * 256 + threadIdx.x;       // [0, 256*256)
    int n = idx >> 8, k = idx & 255;
    dst[idx] = __float2half_rn(W[k * 256 + n]);
}

// ---------------------------------------------------------------------------
// fp16 mma.sync GEMM. Block tile 128 x (16*JT), 128 threads = 4 warps
// (2M x 2N), warp tile 64 x (8*JT). B fp16 in smem; A fp32 (cvt at frag load)
// or fp16 (AHALF). 3-stage cp.async pipeline, one sync per K=32 chunk.
// ---------------------------------------------------------------------------
template<int JT, bool AHALF>
__global__ __launch_bounds__(128, 2) void h16_gemm(
    const void* __restrict__ Av, const __half* __restrict__ Bt,
    const float* __restrict__ bias, float* __restrict__ C, int Ncols)
{
    constexpr int BN = 16 * JT;
    constexpr int AROWB = AHALF ? 80 : 160;       // bytes per A smem row (pitch 40 elems)
    constexpr int ASTAGE = 128 * AROWB;           // bytes per A stage
    constexpr int BSTAGE = BN * 80;               // bytes per B stage (pitch 40 halves)

    extern __shared__ char smraw[];
    char* Abuf = smraw;
    char* Bbuf = smraw + 3 * ASTAGE;
    const uint32_t AsU = smem_u32(Abuf);
    const uint32_t BsU = smem_u32(Bbuf);

    const int tid  = threadIdx.x;
    const int lane = tid & 31;
    const int wid  = tid >> 5;
    const int wm = (wid & 1) * 64;
    const int wn = (wid >> 1) * (8 * JT);
    const int bm = blockIdx.y * 128;
    const int bn = blockIdx.x * BN;

    const int qr = lane >> 2;           // 0..7
    const int qc = lane & 3;            // 0..3

    const float*  Af = (const float*)Av  + (size_t)bm * 256;
    const __half* Ah = (const __half*)Av + (size_t)bm * 256;
    const __half* Bbase = Bt + (size_t)bn * 256;

    float acc[4][JT][4];
    #pragma unroll
    for (int i = 0; i < 4; i++)
        #pragma unroll
        for (int j = 0; j < JT; j++)
            #pragma unroll
            for (int q = 0; q < 4; q++) acc[i][j][q] = 0.f;

    auto issue_chunk = [&](int c, int buf) {
        const uint32_t ab = AsU + buf * ASTAGE;
        const uint32_t bb = BsU + buf * BSTAGE;
        if (AHALF) {
            #pragma unroll
            for (int o = 0; o < 4; o++) {             // 512 x 16B units
                const int u = tid + o * 128;
                const int row = u >> 2, seg = u & 3;
                cp16(ab + row * 80 + seg * 16,
                     Ah + (size_t)row * 256 + c * 32 + seg * 8);
            }
        } else {
            #pragma unroll
            for (int o = 0; o < 8; o++) {             // 1024 x 16B units
                const int u = tid + o * 128;
                const int row = u >> 3, seg = u & 7;
                cp16(ab + row * 160 + seg * 16,
                     Af + (size_t)row * 256 + c * 32 + seg * 4);
            }
        }
        #pragma unroll
        for (int o = 0; o < BN / 32; o++) {           // BN*4 x 16B units
            const int u = tid + o * 128;
            const int row = u >> 2, seg = u & 3;
            cp16(bb + row * 80 + seg * 16,
                 Bbase + (size_t)row * 256 + c * 32 + seg * 8);
        }
        asm volatile("cp.async.commit_group;");
    };

    issue_chunk(0, 0);
    issue_chunk(1, 1);

    #pragma unroll 1
    for (int c = 0; c < 8; c++) {
        __syncthreads();                      // all warps done reading buf (c+2)%3
        if (c + 2 < 8) issue_chunk(c + 2, (c + 2) % 3);
        if (c < 6)      { asm volatile("cp.async.wait_group 2;"); }
        else if (c == 6){ asm volatile("cp.async.wait_group 1;"); }
        else            { asm volatile("cp.async.wait_group 0;"); }
        __syncthreads();                      // chunk c visible to all warps

        const char*   Ac = Abuf + (c % 3) * ASTAGE;
        const __half* Bc = (const __half*)(Bbuf + (c % 3) * BSTAGE);

        #pragma unroll
        for (int ks = 0; ks < 2; ks++) {              // K=16 per mma
            const int kc = ks * 16;
            uint32_t af[4][4], bf[JT][2];
            #pragma unroll
            for (int i = 0; i < 4; i++) {
                if (AHALF) {
                    const __half* ap = (const __half*)Ac + (wm + i * 16 + qr) * 40 + kc + 2 * qc;
                    af[i][0] = *(const uint32_t*)(ap);
                    af[i][1] = *(const uint32_t*)(ap + 8 * 40);
                    af[i][2] = *(const uint32_t*)(ap + 8);
                    af[i][3] = *(const uint32_t*)(ap + 8 * 40 + 8);
                } else {
                    const float* ap = (const float*)Ac + (wm + i * 16 + qr) * 40 + kc + 2 * qc;
                    float2 p0 = *(const float2*)(ap);
                    float2 p1 = *(const float2*)(ap + 8 * 40);
                    float2 p2 = *(const float2*)(ap + 8);
                    float2 p3 = *(const float2*)(ap + 8 * 40 + 8);
                    af[i][0] = pack_h2(p0.x, p0.y);
                    af[i][1] = pack_h2(p1.x, p1.y);
                    af[i][2] = pack_h2(p2.x, p2.y);
                    af[i][3] = pack_h2(p3.x, p3.y);
                }
            }
            #pragma unroll
            for (int j = 0; j < JT; j++) {
                const __half* bp = Bc + (wn + j * 8 + qr) * 40 + kc + 2 * qc;
                bf[j][0] = *(const uint32_t*)(bp);
                bf[j][1] = *(const uint32_t*)(bp + 8);
            }
            #pragma unroll
            for (int i = 0; i < 4; i++)
                #pragma unroll
                for (int j = 0; j < JT; j++)
                    mma_h(acc[i][j], af[i], bf[j]);
        }
    }

    // Epilogue
    #pragma unroll
    for (int i = 0; i < 4; i++) {
        const int r0 = bm + wm + i * 16 + qr;
        #pragma unroll
        for (int j = 0; j < JT; j++) {
            const int col = bn + wn + j * 8 + qc * 2;
            const float b0 = __ldg(&bias[col]), b1 = __ldg(&bias[col + 1]);
            float2 v0 = make_float2(acc[i][j][0] + b0, acc[i][j][1] + b1);
            float2 v1 = make_float2(acc[i][j][2] + b0, acc[i][j][3] + b1);
            *(float2*)(C + (size_t)r0 * Ncols + col) = v0;
            *(float2*)(C + (size_t)(r0 + 8) * Ncols + col) = v1;
        }
    }
}

static constexpr int SMEM_VP  = 3 * (128 * 160 + 128 * 80);  // 92160: JT8, A fp32
static constexpr int SMEM_OUT = 3 * (128 * 80  + 128 * 80);  // 61440: JT8, A fp16
static constexpr int SMEM_QP  = 3 * (128 * 160 + 96  * 80);  // 84480: JT6, A fp32

// ---------------------------------------------------------------------------
// Sampler: ONE warp per query. lane = head*4 + slot; slot covers 8 channels
// (2 x float4 per corner). Branch-free clamped gathers; fp16 output.
// ---------------------------------------------------------------------------
__global__ __launch_bounds__(256) void sample_kernel8(const float* __restrict__ ref)
{
    const int m    = (blockIdx.x * 256 + threadIdx.x) >> 5;   // query
    const int lane = threadIdx.x & 31;
    const int h = lane >> 2;
    const int s = lane & 3;
    const int b = m >> 14;

    const float rx = __ldg(&ref[2 * m + 0]);
    const float ry = __ldg(&ref[2 * m + 1]);

    const float* qp = g_qp + (size_t)m * 128;

    const float4 lg = *(const float4*)(qp + 64 + h * 4);
    const float mx = fmaxf(fmaxf(lg.x, lg.y), fmaxf(lg.z, lg.w));
    const float e0 = __expf(lg.x - mx), e1 = __expf(lg.y - mx);
    const float e2 = __expf(lg.z - mx), e3 = __expf(lg.w - mx);
    const float inv = 1.f / (e0 + e1 + e2 + e3);
    const float w4[4] = {e0 * inv, e1 * inv, e2 * inv, e3 * inv};

    const float4 o01 = *(const float4*)(qp + h * 8);
    const float4 o23 = *(const float4*)(qp + h * 8 + 4);
    const float offx[4] = {o01.x, o01.z, o23.x, o23.z};
    const float offy[4] = {o01.y, o01.w, o23.y, o23.w};

    const float* vb = g_vproj + (size_t)b * HW_ * C_ + h * HD_ + s * 8;

    float a[8] = {0.f, 0.f, 0.f, 0.f, 0.f, 0.f, 0.f, 0.f};

    #pragma unroll
    for (int p = 0; p < 4; p++) {
        const float lx = fminf(fmaxf(rx + offx[p] * (0.1f / W_), 0.f), 1.f);
        const float ly = fminf(fmaxf(ry + offy[p] * (0.1f / H_), 0.f), 1.f);
        const float ixf = lx * (float)W_ - 0.5f;
        const float iyf = ly * (float)H_ - 0.5f;
        const float x0f = floorf(ixf), y0f = floorf(iyf);
        const float wx = ixf - x0f, wy = iyf - y0f;
        const int x0 = (int)x0f, y0 = (int)y0f;    // in [-1,127]

        const float mx0 = (x0 >= 0)      ? 1.f : 0.f;
        const float mx1 = (x0 + 1 < W_)  ? 1.f : 0.f;
        const float my0 = (y0 >= 0)      ? 1.f : 0.f;
        const float my1 = (y0 + 1 < H_)  ? 1.f : 0.f;

        const int x0c = max(x0, 0),     x1c = min(x0 + 1, W_ - 1);
        const int y0c = max(y0, 0),     y1c = min(y0 + 1, H_ - 1);

        const float wp  = w4[p];
        const float c00 = wp * (1.f - wx) * (1.f - wy) * mx0 * my0;
        const float c10 = wp *        wx  * (1.f - wy) * mx1 * my0;
        const float c01 = wp * (1.f - wx) *        wy  * mx0 * my1;
        const float c11 = wp *        wx  *        wy  * mx1 * my1;

        const float* p00 = vb + (size_t)(y0c * W_ + x0c) * C_;
        const float* p10 = vb + (size_t)(y0c * W_ + x1c) * C_;
        const float* p01 = vb + (size_t)(y1c * W_ + x0c) * C_;
        const float* p11 = vb + (size_t)(y1c * W_ + x1c) * C_;

        const float4 u00 = *(const float4*)(p00),     v00 = *(const float4*)(p00 + 4);
        const float4 u10 = *(const float4*)(p10),     v10 = *(const float4*)(p10 + 4);
        const float4 u01 = *(const float4*)(p01),     v01 = *(const float4*)(p01 + 4);
        const float4 u11 = *(const float4*)(p11),     v11 = *(const float4*)(p11 + 4);

        a[0] = fmaf(c00, u00.x, fmaf(c10, u10.x, fmaf(c01, u01.x, fmaf(c11, u11.x, a[0]))));
        a[1] = fmaf(c00, u00.y, fmaf(c10, u10.y, fmaf(c01, u01.y, fmaf(c11, u11.y, a[1]))));
        a[2] = fmaf(c00, u00.z, fmaf(c10, u10.z, fmaf(c01, u01.z, fmaf(c11, u11.z, a[2]))));
        a[3] = fmaf(c00, u00.w, fmaf(c10, u10.w, fmaf(c01, u01.w, fmaf(c11, u11.w, a[3]))));
        a[4] = fmaf(c00, v00.x, fmaf(c10, v10.x, fmaf(c01, v01.x, fmaf(c11, v11.x, a[4]))));
        a[5] = fmaf(c00, v00.y, fmaf(c10, v10.y, fmaf(c01, v01.y, fmaf(c11, v11.y, a[5]))));
        a[6] = fmaf(c00, v00.z, fmaf(c10, v10.z, fmaf(c01, v01.z, fmaf(c11, v11.z, a[6]))));
        a[7] = fmaf(c00, v00.w, fmaf(c10, v10.w, fmaf(c01, v01.w, fmaf(c11, v11.w, a[7]))));
    }

    uint4 o;
    o.x = pack_h2(a[0], a[1]);
    o.y = pack_h2(a[2], a[3]);
    o.z = pack_h2(a[4], a[5]);
    o.w = pack_h2(a[6], a[7]);
    *(uint4*)(g_sampled_h + (size_t)m * C_ + h * HD_ + s * 8) = o;
}

// ---------------------------------------------------------------------------
extern "C" void kernel_launch(void* const* d_in, const int* in_sizes, int n_in,
                              void* d_out, int out_size)
{
    const float* query  = (const float*)d_in[0];
    const float* refp   = (const float*)d_in[1];
    const float* value  = (const float*)d_in[2];
    const float* W_off  = (const float*)d_in[3];
    const float* b_off  = (const float*)d_in[4];
    const float* W_attn = (const float*)d_in[5];
    const float* b_attn = (const float*)d_in[6];
    const float* W_v    = (const float*)d_in[7];
    const float* b_v    = (const float*)d_in[8];
    const float* W_out  = (const float*)d_in[9];
    const float* b_out  = (const float*)d_in[10];
    float* out = (float*)d_out;

    float *p_qp, *p_vp, *p_bqp;
    __half *p_s, *p_Wqpt, *p_Wvt, *p_Wot;
    cudaGetSymbolAddress((void**)&p_qp,   g_qp);
    cudaGetSymbolAddress((void**)&p_vp,   g_vproj);
    cudaGetSymbolAddress((void**)&p_s,    g_sampled_h);
    cudaGetSymbolAddress((void**)&p_Wqpt, g_Wqpt_h);
    cudaGetSymbolAddress((void**)&p_bqp,  g_bqp);
    cudaGetSymbolAddress((void**)&p_Wvt,  g_Wvt_h);
    cudaGetSymbolAddress((void**)&p_Wot,  g_Wot_h);

    cudaFuncSetAttribute((const void*)h16_gemm<8, false>, cudaFuncAttributeMaxDynamicSharedMemorySize, SMEM_VP);
    cudaFuncSetAttribute((const void*)h16_gemm<8, true>,  cudaFuncAttributeMaxDynamicSharedMemorySize, SMEM_OUT);
    cudaFuncSetAttribute((const void*)h16_gemm<6, false>, cudaFuncAttributeMaxDynamicSharedMemorySize, SMEM_QP);

    // 0) pack/transpose/convert weights
    pack_qp_t<<<96, 256>>>(W_off, b_off, W_attn, b_attn);
    pack_t256<<<256, 256>>>(W_v, p_Wvt);
    pack_t256<<<256, 256>>>(W_out, p_Wot);
    // 1) fused offset+logit projection: [M,256] x [256,96] -> g_qp (pitch 128)
    h16_gemm<6, false><<<dim3(1, M_ / 128), 128, SMEM_QP>>>(query, p_Wqpt, p_bqp, p_qp, 128);
    // 2) value projection: [M,256] x [256,256]
    h16_gemm<8, false><<<dim3(2, M_ / 128), 128, SMEM_VP>>>(value, p_Wvt, b_v, p_vp, 256);
    // 3) softmax + bilinear deformable sampling -> fp16
    sample_kernel8<<<M_ / 8, 256>>>(refp);
    // 4) output projection (fp16 A) -> d_out
    h16_gemm<8, true><<<dim3(2, M_ / 128), 128, SMEM_OUT>>>(p_s, p_Wot, b_out, out, 256);
}

// round 9
// speedup vs baseline: 1.5018x; 1.1614x over previous
#include <cuda_runtime.h>
#include <cuda_fp16.h>
#include <cstdint>

// Problem constants (fixed by the dataset)
#define B_   4
#define NQ_  16384
#define C_   256
#define NH_  8
#define NP_  4
#define H_   128
#define W_   128
#define HD_  32
#define M_   (B_ * NQ_)      // 65536 rows
#define HW_  (H_ * W_)       // 16384

// Scratch (__device__ globals: allocation-free rule)
__device__ float  g_qp       [(size_t)M_ * 96];        // [M, 64 off | 32 logits]
__device__ __half g_vproj_h  [(size_t)B_ * HW_ * C_];  // [B, HW, C] fp16
__device__ __half g_sampled_h[(size_t)M_ * C_];        // [M, C] fp16
__device__ __half g_Wqpt_h   [96 * 256];               // packed W_off|W_attn, [N,K] fp16
__device__ float  g_bqp      [96];
__device__ __half g_Wvt_h    [256 * 256];              // W_v^T  [N,K] fp16
__device__ __half g_Wot_h    [256 * 256];              // W_out^T [N,K] fp16

__device__ __forceinline__ uint32_t smem_u32(const void* p) {
    uint32_t a;
    asm("{ .reg .u64 t; cvta.to.shared.u64 t, %1; cvt.u32.u64 %0, t; }" : "=r"(a) : "l"(p));
    return a;
}
__device__ __forceinline__ void cp16(uint32_t dst, const void* src) {
    asm volatile("cp.async.cg.shared.global [%0], [%1], 16;" :: "r"(dst), "l"(src));
}
// pack two fp32 -> f16x2 (lo = first elem, hi = second)
__device__ __forceinline__ uint32_t pack_h2(float lo, float hi) {
    uint32_t r;
    asm("cvt.rn.f16x2.f32 %0, %1, %2;" : "=r"(r) : "f"(hi), "f"(lo));
    return r;
}

// m16n8k16 fp16 MMA, fp32 accumulate
__device__ __forceinline__ void mma_h(float* d, const uint32_t* a, const uint32_t* b) {
    asm volatile(
        "mma.sync.aligned.m16n8k16.row.col.f32.f16.f16.f32 "
        "{%0,%1,%2,%3}, {%4,%5,%6,%7}, {%8,%9}, {%0,%1,%2,%3};"
        : "+f"(d[0]), "+f"(d[1]), "+f"(d[2]), "+f"(d[3])
        : "r"(a[0]), "r"(a[1]), "r"(a[2]), "r"(a[3]), "r"(b[0]), "r"(b[1]));
}

// ---------------------------------------------------------------------------
// Pack kernels: transpose weights to [N,K] (K contiguous), convert to fp16.
// ---------------------------------------------------------------------------
__global__ void pack_qp_t(const float* __restrict__ W_off, const float* __restrict__ b_off,
                          const float* __restrict__ W_attn, const float* __restrict__ b_attn)
{
    int idx = blockIdx.x * 256 + threadIdx.x;       // [0, 96*256)
    int n = idx >> 8, k = idx & 255;
    float v = (n < 64) ? W_off[k * 64 + n] : W_attn[k * 32 + (n - 64)];
    g_Wqpt_h[idx] = __float2half_rn(v);
    if (idx < 96)
        g_bqp[idx] = (idx < 64) ? b_off[idx] : b_attn[idx - 64];
}
__global__ void pack_t256(const float* __restrict__ W, __half* __restrict__ dst)
{
    int idx = blockIdx.x * 256 + threadIdx.x;       // [0, 256*256)
    int n = idx >> 8, k = idx & 255;
    dst[idx] = __float2half_rn(W[k * 256 + n]);
}

// ---------------------------------------------------------------------------
// fp16 mma.sync GEMM. Block tile 128 x (16*JT), 128 threads = 4 warps
// (2M x 2N), warp tile 64 x (8*JT). B fp16 in smem; A fp32 (cvt at frag load)
// or fp16 (AHALF). Output fp32 or fp16 (CHALF).
// 3-stage cp.async pipeline with ONE __syncthreads per K=32 chunk:
//   wait_group (chunk c done, per-thread) -> sync (publish c block-wide AND
//   prove all warps past compute(c-1)) -> issue c+2 into c-1's buffer -> compute c.
// ---------------------------------------------------------------------------
template<int JT, bool AHALF, bool CHALF>
__global__ __launch_bounds__(128, 2) void h16_gemm(
    const void* __restrict__ Av, const __half* __restrict__ Bt,
    const float* __restrict__ bias, void* __restrict__ Cv, int Ncols)
{
    constexpr int BN = 16 * JT;
    constexpr int AROWB = AHALF ? 80 : 160;       // bytes per A smem row (pitch 40 elems)
    constexpr int ASTAGE = 128 * AROWB;
    constexpr int BSTAGE = BN * 80;               // pitch 40 halves

    extern __shared__ char smraw[];
    char* Abuf = smraw;
    char* Bbuf = smraw + 3 * ASTAGE;
    const uint32_t AsU = smem_u32(Abuf);
    const uint32_t BsU = smem_u32(Bbuf);

    const int tid  = threadIdx.x;
    const int lane = tid & 31;
    const int wid  = tid >> 5;
    const int wm = (wid & 1) * 64;
    const int wn = (wid >> 1) * (8 * JT);
    const int bm = blockIdx.y * 128;
    const int bn = blockIdx.x * BN;

    const int qr = lane >> 2;           // 0..7
    const int qc = lane & 3;            // 0..3

    const float*  Af = (const float*)Av  + (size_t)bm * 256;
    const __half* Ah = (const __half*)Av + (size_t)bm * 256;
    const __half* Bbase = Bt + (size_t)bn * 256;

    float acc[4][JT][4];
    #pragma unroll
    for (int i = 0; i < 4; i++)
        #pragma unroll
        for (int j = 0; j < JT; j++)
            #pragma unroll
            for (int q = 0; q < 4; q++) acc[i][j][q] = 0.f;

    auto issue_chunk = [&](int c, int buf) {
        const uint32_t ab = AsU + buf * ASTAGE;
        const uint32_t bb = BsU + buf * BSTAGE;
        if (AHALF) {
            #pragma unroll
            for (int o = 0; o < 4; o++) {
                const int u = tid + o * 128;
                const int row = u >> 2, seg = u & 3;
                cp16(ab + row * 80 + seg * 16,
                     Ah + (size_t)row * 256 + c * 32 + seg * 8);
            }
        } else {
            #pragma unroll
            for (int o = 0; o < 8; o++) {
                const int u = tid + o * 128;
                const int row = u >> 3, seg = u & 7;
                cp16(ab + row * 160 + seg * 16,
                     Af + (size_t)row * 256 + c * 32 + seg * 4);
            }
        }
        #pragma unroll
        for (int o = 0; o < BN / 32; o++) {
            const int u = tid + o * 128;
            const int row = u >> 2, seg = u & 3;
            cp16(bb + row * 80 + seg * 16,
                 Bbase + (size_t)row * 256 + c * 32 + seg * 8);
        }
        asm volatile("cp.async.commit_group;");
    };

    issue_chunk(0, 0);
    issue_chunk(1, 1);

    #pragma unroll 1
    for (int c = 0; c < 8; c++) {
        if (c < 7) { asm volatile("cp.async.wait_group 1;"); }
        else       { asm volatile("cp.async.wait_group 0;"); }
        __syncthreads();
        if (c + 2 < 8) issue_chunk(c + 2, (c + 2) % 3);

        const char*   Ac = Abuf + (c % 3) * ASTAGE;
        const __half* Bc = (const __half*)(Bbuf + (c % 3) * BSTAGE);

        #pragma unroll
        for (int ks = 0; ks < 2; ks++) {              // K=16 per mma
            const int kc = ks * 16;
            uint32_t af[4][4], bf[JT][2];
            #pragma unroll
            for (int i = 0; i < 4; i++) {
                if (AHALF) {
                    const __half* ap = (const __half*)Ac + (wm + i * 16 + qr) * 40 + kc + 2 * qc;
                    af[i][0] = *(const uint32_t*)(ap);
                    af[i][1] = *(const uint32_t*)(ap + 8 * 40);
                    af[i][2] = *(const uint32_t*)(ap + 8);
                    af[i][3] = *(const uint32_t*)(ap + 8 * 40 + 8);
                } else {
                    const float* ap = (const float*)Ac + (wm + i * 16 + qr) * 40 + kc + 2 * qc;
                    float2 p0 = *(const float2*)(ap);
                    float2 p1 = *(const float2*)(ap + 8 * 40);
                    float2 p2 = *(const float2*)(ap + 8);
                    float2 p3 = *(const float2*)(ap + 8 * 40 + 8);
                    af[i][0] = pack_h2(p0.x, p0.y);
                    af[i][1] = pack_h2(p1.x, p1.y);
                    af[i][2] = pack_h2(p2.x, p2.y);
                    af[i][3] = pack_h2(p3.x, p3.y);
                }
            }
            #pragma unroll
            for (int j = 0; j < JT; j++) {
                const __half* bp = Bc + (wn + j * 8 + qr) * 40 + kc + 2 * qc;
                bf[j][0] = *(const uint32_t*)(bp);
                bf[j][1] = *(const uint32_t*)(bp + 8);
            }
            #pragma unroll
            for (int i = 0; i < 4; i++)
                #pragma unroll
                for (int j = 0; j < JT; j++)
                    mma_h(acc[i][j], af[i], bf[j]);
        }
    }

    // Epilogue
    #pragma unroll
    for (int i = 0; i < 4; i++) {
        const int r0 = bm + wm + i * 16 + qr;
        #pragma unroll
        for (int j = 0; j < JT; j++) {
            const int col = bn + wn + j * 8 + qc * 2;
            const float b0 = __ldg(&bias[col]), b1 = __ldg(&bias[col + 1]);
            const float v00 = acc[i][j][0] + b0, v01 = acc[i][j][1] + b1;
            const float v10 = acc[i][j][2] + b0, v11 = acc[i][j][3] + b1;
            if (CHALF) {
                __half* Ch = (__half*)Cv;
                *(uint32_t*)(Ch + (size_t)r0 * Ncols + col)       = pack_h2(v00, v01);
                *(uint32_t*)(Ch + (size_t)(r0 + 8) * Ncols + col) = pack_h2(v10, v11);
            } else {
                float* Cf = (float*)Cv;
                *(float2*)(Cf + (size_t)r0 * Ncols + col)       = make_float2(v00, v01);
                *(float2*)(Cf + (size_t)(r0 + 8) * Ncols + col) = make_float2(v10, v11);
            }
        }
    }
}

static constexpr int SMEM_VP  = 3 * (128 * 160 + 128 * 80);  // 92160: JT8, A fp32
static constexpr int SMEM_OUT = 3 * (128 * 80  + 128 * 80);  // 61440: JT8, A fp16
static constexpr int SMEM_QP  = 3 * (128 * 160 + 96  * 80);  // 84480: JT6, A fp32

// ---------------------------------------------------------------------------
// Sampler: ONE warp per query. lane = head*4 + slot; slot covers 8 channels.
// vproj is fp16: each corner = one 16B load; fp32 accumulation; fp16 output.
// ---------------------------------------------------------------------------
__global__ __launch_bounds__(256) void sample_kernel8(const float* __restrict__ ref)
{
    const int m    = (blockIdx.x * 256 + threadIdx.x) >> 5;   // query
    const int lane = threadIdx.x & 31;
    const int h = lane >> 2;
    const int s = lane & 3;
    const int b = m >> 14;

    const float rx = __ldg(&ref[2 * m + 0]);
    const float ry = __ldg(&ref[2 * m + 1]);

    const float* qp = g_qp + (size_t)m * 96;

    const float4 lg = *(const float4*)(qp + 64 + h * 4);
    const float mx = fmaxf(fmaxf(lg.x, lg.y), fmaxf(lg.z, lg.w));
    const float e0 = __expf(lg.x - mx), e1 = __expf(lg.y - mx);
    const float e2 = __expf(lg.z - mx), e3 = __expf(lg.w - mx);
    const float inv = 1.f / (e0 + e1 + e2 + e3);
    const float w4[4] = {e0 * inv, e1 * inv, e2 * inv, e3 * inv};

    const float4 o01 = *(const float4*)(qp + h * 8);
    const float4 o23 = *(const float4*)(qp + h * 8 + 4);
    const float offx[4] = {o01.x, o01.z, o23.x, o23.z};
    const float offy[4] = {o01.y, o01.w, o23.y, o23.w};

    const __half* vb = g_vproj_h + (size_t)b * HW_ * C_ + h * HD_ + s * 8;

    float a[8] = {0.f, 0.f, 0.f, 0.f, 0.f, 0.f, 0.f, 0.f};

    #pragma unroll
    for (int p = 0; p < 4; p++) {
        const float lx = fminf(fmaxf(rx + offx[p] * (0.1f / W_), 0.f), 1.f);
        const float ly = fminf(fmaxf(ry + offy[p] * (0.1f / H_), 0.f), 1.f);
        const float ixf = lx * (float)W_ - 0.5f;
        const float iyf = ly * (float)H_ - 0.5f;
        const float x0f = floorf(ixf), y0f = floorf(iyf);
        const float wx = ixf - x0f, wy = iyf - y0f;
        const int x0 = (int)x0f, y0 = (int)y0f;    // in [-1,127]

        const float mx0 = (x0 >= 0)      ? 1.f : 0.f;
        const float mx1 = (x0 + 1 < W_)  ? 1.f : 0.f;
        const float my0 = (y0 >= 0)      ? 1.f : 0.f;
        const float my1 = (y0 + 1 < H_)  ? 1.f : 0.f;

        const int x0c = max(x0, 0),     x1c = min(x0 + 1, W_ - 1);
        const int y0c = max(y0, 0),     y1c = min(y0 + 1, H_ - 1);

        const float wp  = w4[p];
        const float c00 = wp * (1.f - wx) * (1.f - wy) * mx0 * my0;
        const float c10 = wp *        wx  * (1.f - wy) * mx1 * my0;
        const float c01 = wp * (1.f - wx) *        wy  * mx0 * my1;
        const float c11 = wp *        wx  *        wy  * mx1 * my1;

        const uint4 r00 = *(const uint4*)(vb + (size_t)(y0c * W_ + x0c) * C_);
        const uint4 r10 = *(const uint4*)(vb + (size_t)(y0c * W_ + x1c) * C_);
        const uint4 r01 = *(const uint4*)(vb + (size_t)(y1c * W_ + x0c) * C_);
        const uint4 r11 = *(const uint4*)(vb + (size_t)(y1c * W_ + x1c) * C_);

        #pragma unroll
        for (int q = 0; q < 4; q++) {
            const float2 f00 = __half22float2(((const __half2*)&r00)[q]);
            const float2 f10 = __half22float2(((const __half2*)&r10)[q]);
            const float2 f01 = __half22float2(((const __half2*)&r01)[q]);
            const float2 f11 = __half22float2(((const __half2*)&r11)[q]);
            a[2*q+0] = fmaf(c00, f00.x, fmaf(c10, f10.x, fmaf(c01, f01.x, fmaf(c11, f11.x, a[2*q+0]))));
            a[2*q+1] = fmaf(c00, f00.y, fmaf(c10, f10.y, fmaf(c01, f01.y, fmaf(c11, f11.y, a[2*q+1]))));
        }
    }

    uint4 o;
    o.x = pack_h2(a[0], a[1]);
    o.y = pack_h2(a[2], a[3]);
    o.z = pack_h2(a[4], a[5]);
    o.w = pack_h2(a[6], a[7]);
    *(uint4*)(g_sampled_h + (size_t)m * C_ + h * HD_ + s * 8) = o;
}

// ---------------------------------------------------------------------------
extern "C" void kernel_launch(void* const* d_in, const int* in_sizes, int n_in,
                              void* d_out, int out_size)
{
    const float* query  = (const float*)d_in[0];
    const float* refp   = (const float*)d_in[1];
    const float* value  = (const float*)d_in[2];
    const float* W_off  = (const float*)d_in[3];
    const float* b_off  = (const float*)d_in[4];
    const float* W_attn = (const float*)d_in[5];
    const float* b_attn = (const float*)d_in[6];
    const float* W_v    = (const float*)d_in[7];
    const float* b_v    = (const float*)d_in[8];
    const float* W_out  = (const float*)d_in[9];
    const float* b_out  = (const float*)d_in[10];
    float* out = (float*)d_out;

    float *p_qp, *p_bqp;
    __half *p_vp, *p_s, *p_Wqpt, *p_Wvt, *p_Wot;
    cudaGetSymbolAddress((void**)&p_qp,   g_qp);
    cudaGetSymbolAddress((void**)&p_vp,   g_vproj_h);
    cudaGetSymbolAddress((void**)&p_s,    g_sampled_h);
    cudaGetSymbolAddress((void**)&p_Wqpt, g_Wqpt_h);
    cudaGetSymbolAddress((void**)&p_bqp,  g_bqp);
    cudaGetSymbolAddress((void**)&p_Wvt,  g_Wvt_h);
    cudaGetSymbolAddress((void**)&p_Wot,  g_Wot_h);

    cudaFuncSetAttribute((const void*)h16_gemm<6, false, false>, cudaFuncAttributeMaxDynamicSharedMemorySize, SMEM_QP);
    cudaFuncSetAttribute((const void*)h16_gemm<8, false, true>,  cudaFuncAttributeMaxDynamicSharedMemorySize, SMEM_VP);
    cudaFuncSetAttribute((const void*)h16_gemm<8, true,  false>, cudaFuncAttributeMaxDynamicSharedMemorySize, SMEM_OUT);

    // 0) pack/transpose/convert weights
    pack_qp_t<<<96, 256>>>(W_off, b_off, W_attn, b_attn);
    pack_t256<<<256, 256>>>(W_v, p_Wvt);
    pack_t256<<<256, 256>>>(W_out, p_Wot);
    // 1) fused offset+logit projection: [M,256] x [256,96] -> g_qp (pitch 96)
    h16_gemm<6, false, false><<<dim3(1, M_ / 128), 128, SMEM_QP>>>(query, p_Wqpt, p_bqp, p_qp, 96);
    // 2) value projection: [M,256] x [256,256] -> fp16
    h16_gemm<8, false, true><<<dim3(2, M_ / 128), 128, SMEM_VP>>>(value, p_Wvt, b_v, p_vp, 256);
    // 3) softmax + bilinear deformable sampling (fp16 in/out)
    sample_kernel8<<<M_ / 8, 256>>>(refp);
    // 4) output projection (fp16 A) -> d_out
    h16_gemm<8, true, false><<<dim3(2, M_ / 128), 128, SMEM_OUT>>>(p_s, p_Wot, b_out, out, 256);
}